// round 16
// baseline (speedup 1.0000x reference)
#include <cuda_runtime.h>
#include <float.h>

// ROI max pooling, exact integer-bin partition (matches reference):
//   cell (py,px) of roi (y0,x0,h,w) covers rows [y0 + py*h/7, y0 + (py+1)*h/7)
//   and cols [x0 + px*w/7, x0 + (px+1)*w/7). h,w >= 7 so cells are non-empty.
//
// Shapes: feature_map [B=2, H=38, W=38, C=512] f32, rois [B=2, N=64, 4] i32,
// out [B, N, 7, 7, C] f32.
//
// R14 -> R15: six structural variants bracket R4 as optimal; model says we
// are bound by SM-level load pipe at a rate set by avg L1/L2 latency blend.
// Restore exact R4 shell; add zero-overhead cache-policy hints:
//   - fm loads:  ld.global.nc.L1::evict_last (retain hot shared fm lines)
//   - out store: st.global.cs (streaming; don't displace fm in L1/L2)

#define H_DIM 38
#define W_DIM 38
#define C4 128           // C/4 float4 groups per pixel
#define POOL 7
#define ROWSTRIDE (W_DIM * C4)

__device__ __forceinline__ float4 ldg_el(const float4* p) {
    float4 v;
    asm("ld.global.nc.L1::evict_last.v4.f32 {%0,%1,%2,%3}, [%4];"
        : "=f"(v.x), "=f"(v.y), "=f"(v.z), "=f"(v.w) : "l"(p));
    return v;
}

__device__ __forceinline__ void stg_cs(float4* p, float4 v) {
    asm volatile("st.global.cs.v4.f32 [%0], {%1,%2,%3,%4};"
                 :: "l"(p), "f"(v.x), "f"(v.y), "f"(v.z), "f"(v.w) : "memory");
}

__device__ __forceinline__ void fmax4(float4& m, const float4 v) {
    m.x = fmaxf(m.x, v.x);
    m.y = fmaxf(m.y, v.y);
    m.z = fmaxf(m.z, v.z);
    m.w = fmaxf(m.w, v.w);
}

__global__ __launch_bounds__(32) void roi_pool_kernel(
    const float4* __restrict__ fm,   // [B, H, W, C/4] as float4
    const int*    __restrict__ rois, // [B*N, 4] (y, x, h, w)
    float4*       __restrict__ out,  // [B*N, 49, C/4] as float4
    int n_per_b)                     // N (rois per batch)
{
    const int cell = blockIdx.x;        // roi*49 + py*7 + px
    const int px   = cell % POOL;
    const int py   = (cell / POOL) % POOL;
    const int roi  = cell / (POOL * POOL);
    const int b    = roi / n_per_b;

    const int4 r = __ldg((const int4*)(rois + roi * 4));
    const int y0 = r.x, x0 = r.y, h = r.z, w = r.w;

    const int ys = y0 + (py * h) / POOL;
    const int ye = y0 + ((py + 1) * h) / POOL;
    const int xs = x0 + (px * w) / POOL;
    const int xe = x0 + ((px + 1) * w) / POOL;

    // channel half: block gy handles float4 slots [gy*64, gy*64+64)
    const int c = (blockIdx.y << 6) + threadIdx.x;
    const float4* base = fm + ((size_t)b * H_DIM * W_DIM) * C4 + c;

    float4 m0 = make_float4(-FLT_MAX, -FLT_MAX, -FLT_MAX, -FLT_MAX);
    float4 m1 = m0;

    int y = ys;
    // ---- y-unroll 2, x-unroll 2: 8 independent LDG.128 per iteration ----
    for (; y + 1 < ye; y += 2) {
        const float4* p0 = base + ((size_t)(y * W_DIM + xs)) * C4;
        const float4* p1 = p0 + ROWSTRIDE;
        int x = xs;
        for (; x + 1 < xe; x += 2, p0 += 2 * C4, p1 += 2 * C4) {
            float4 a0 = ldg_el(p0);
            float4 a1 = ldg_el(p0 + 32);
            float4 a2 = ldg_el(p0 + C4);
            float4 a3 = ldg_el(p0 + C4 + 32);
            float4 b0 = ldg_el(p1);
            float4 b1 = ldg_el(p1 + 32);
            float4 b2 = ldg_el(p1 + C4);
            float4 b3 = ldg_el(p1 + C4 + 32);
            fmax4(m0, a0); fmax4(m1, a1);
            fmax4(m0, a2); fmax4(m1, a3);
            fmax4(m0, b0); fmax4(m1, b1);
            fmax4(m0, b2); fmax4(m1, b3);
        }
        if (x < xe) {
            float4 a0 = ldg_el(p0);
            float4 a1 = ldg_el(p0 + 32);
            float4 b0 = ldg_el(p1);
            float4 b1 = ldg_el(p1 + 32);
            fmax4(m0, a0); fmax4(m1, a1);
            fmax4(m0, b0); fmax4(m1, b1);
        }
    }
    // ---- remainder row (odd cell height), x-unroll 2 ----
    if (y < ye) {
        const float4* p0 = base + ((size_t)(y * W_DIM + xs)) * C4;
        int x = xs;
        for (; x + 1 < xe; x += 2, p0 += 2 * C4) {
            float4 a0 = ldg_el(p0);
            float4 a1 = ldg_el(p0 + 32);
            float4 a2 = ldg_el(p0 + C4);
            float4 a3 = ldg_el(p0 + C4 + 32);
            fmax4(m0, a0); fmax4(m1, a1);
            fmax4(m0, a2); fmax4(m1, a3);
        }
        if (x < xe) {
            float4 a0 = ldg_el(p0);
            float4 a1 = ldg_el(p0 + 32);
            fmax4(m0, a0); fmax4(m1, a1);
        }
    }

    float4* o = out + (size_t)cell * C4 + c;
    stg_cs(o, m0);
    stg_cs(o + 32, m1);
}

extern "C" void kernel_launch(void* const* d_in, const int* in_sizes, int n_in,
                              void* d_out, int out_size) {
    const float4* fm   = (const float4*)d_in[0];
    const int*    rois = (const int*)d_in[1];
    float4*       out  = (float4*)d_out;

    const int n_rois  = in_sizes[1] / 4;     // B*N = 128
    const int B       = 2;                   // fixed per problem shapes
    const int n_per_b = n_rois / B;          // N = 64

    dim3 grid(n_rois * POOL * POOL, 2);      // 6272 cells x 2 channel halves
    roi_pool_kernel<<<grid, 32>>>(fm, rois, out, n_per_b);
}

// round 17
// speedup vs baseline: 1.4234x; 1.4234x over previous
#include <cuda_runtime.h>
#include <float.h>

// ROI max pooling, exact integer-bin partition (matches reference):
//   cell (py,px) of roi (y0,x0,h,w) covers rows [y0 + py*h/7, y0 + (py+1)*h/7)
//   and cols [x0 + px*w/7, x0 + (px+1)*w/7). h,w >= 7 so cells are non-empty.
//
// Shapes: feature_map [B=2, H=38, W=38, C=512] f32, rois [B=2, N=64, 4] i32,
// out [B, N, 7, 7, C] f32.
//
// R15 -> R16: cache hints reverted (neutral kernel, bench regression).
// Mechanism consistent with all 16 rounds: per-warp-lifetime SERIAL chain
// (roi load -> bounds -> first pixel loads) dominates small cells. This
// round: 2 units per warp (6272 warps), both rois' int4 loads issued
// back-to-back at t=0 (latencies overlap), unit2 bounds precomputed before
// unit1 streams. Pairing i with i+6272 also averages two random rois'
// durations -> halves imbalance variance. Body = proven R4 y2x2 shell.

#define H_DIM 38
#define W_DIM 38
#define C4 128           // C/4 float4 groups per pixel
#define POOL 7
#define ROWSTRIDE (W_DIM * C4)
#define NCELL (POOL * POOL)

__device__ __forceinline__ void fmax4(float4& m, const float4 v) {
    m.x = fmaxf(m.x, v.x);
    m.y = fmaxf(m.y, v.y);
    m.z = fmaxf(m.z, v.z);
    m.w = fmaxf(m.w, v.w);
}

// Process one cell (bounds already computed) with the R4-proven y2x2 body.
__device__ __forceinline__ void do_cell(
    const float4* __restrict__ base,   // fm + batch offset + channel c
    float4* __restrict__ o,            // out + cell*C4 + c
    int ys, int ye, int xs, int xe)
{
    float4 m0 = make_float4(-FLT_MAX, -FLT_MAX, -FLT_MAX, -FLT_MAX);
    float4 m1 = m0;

    int y = ys;
    for (; y + 1 < ye; y += 2) {
        const float4* p0 = base + ((size_t)(y * W_DIM + xs)) * C4;
        const float4* p1 = p0 + ROWSTRIDE;
        int x = xs;
        for (; x + 1 < xe; x += 2, p0 += 2 * C4, p1 += 2 * C4) {
            float4 a0 = __ldg(p0);
            float4 a1 = __ldg(p0 + 32);
            float4 a2 = __ldg(p0 + C4);
            float4 a3 = __ldg(p0 + C4 + 32);
            float4 b0 = __ldg(p1);
            float4 b1 = __ldg(p1 + 32);
            float4 b2 = __ldg(p1 + C4);
            float4 b3 = __ldg(p1 + C4 + 32);
            fmax4(m0, a0); fmax4(m1, a1);
            fmax4(m0, a2); fmax4(m1, a3);
            fmax4(m0, b0); fmax4(m1, b1);
            fmax4(m0, b2); fmax4(m1, b3);
        }
        if (x < xe) {
            float4 a0 = __ldg(p0);
            float4 a1 = __ldg(p0 + 32);
            float4 b0 = __ldg(p1);
            float4 b1 = __ldg(p1 + 32);
            fmax4(m0, a0); fmax4(m1, a1);
            fmax4(m0, b0); fmax4(m1, b1);
        }
    }
    if (y < ye) {
        const float4* p0 = base + ((size_t)(y * W_DIM + xs)) * C4;
        int x = xs;
        for (; x + 1 < xe; x += 2, p0 += 2 * C4) {
            float4 a0 = __ldg(p0);
            float4 a1 = __ldg(p0 + 32);
            float4 a2 = __ldg(p0 + C4);
            float4 a3 = __ldg(p0 + C4 + 32);
            fmax4(m0, a0); fmax4(m1, a1);
            fmax4(m0, a2); fmax4(m1, a3);
        }
        if (x < xe) {
            float4 a0 = __ldg(p0);
            float4 a1 = __ldg(p0 + 32);
            fmax4(m0, a0); fmax4(m1, a1);
        }
    }

    o[0]  = m0;
    o[32] = m1;
}

__global__ __launch_bounds__(32) void roi_pool_kernel(
    const float4* __restrict__ fm,   // [B, H, W, C/4] as float4
    const int*    __restrict__ rois, // [B*N, 4] (y, x, h, w)
    float4*       __restrict__ out,  // [B*N, 49, C/4] as float4
    int n_per_b)                     // N (rois per batch)
{
    // unit = cell*2 + half; this warp handles unit u and u + 6272.
    // u = blockIdx.x*2 + blockIdx.y keeps both units' rois uncorrelated.
    const int u1 = blockIdx.x * 2 + blockIdx.y;
    const int u2 = u1 + NCELL * 128;           // + 6272 (B*N*49*2 / 2)

    // ---- prologue for BOTH units up front: roi loads overlap ----
    const int cell1 = u1 >> 1, half1 = u1 & 1;
    const int cell2 = u2 >> 1, half2 = u2 & 1;
    const int roi1 = cell1 / NCELL, roi2 = cell2 / NCELL;

    const int4 r1 = __ldg((const int4*)(rois + roi1 * 4));
    const int4 r2 = __ldg((const int4*)(rois + roi2 * 4));

    const int pc1 = cell1 % NCELL, pc2 = cell2 % NCELL;
    const int py1 = pc1 / POOL, px1 = pc1 % POOL;
    const int py2 = pc2 / POOL, px2 = pc2 % POOL;
    const int b1 = roi1 / n_per_b, b2 = roi2 / n_per_b;

    const int ys1 = r1.x + (py1 * r1.z) / POOL;
    const int ye1 = r1.x + ((py1 + 1) * r1.z) / POOL;
    const int xs1 = r1.y + (px1 * r1.w) / POOL;
    const int xe1 = r1.y + ((px1 + 1) * r1.w) / POOL;

    const int ys2 = r2.x + (py2 * r2.z) / POOL;
    const int ye2 = r2.x + ((py2 + 1) * r2.z) / POOL;
    const int xs2 = r2.y + (px2 * r2.w) / POOL;
    const int xe2 = r2.y + ((px2 + 1) * r2.w) / POOL;

    const int c1 = (half1 << 6) + threadIdx.x;
    const int c2 = (half2 << 6) + threadIdx.x;

    do_cell(fm + ((size_t)b1 * H_DIM * W_DIM) * C4 + c1,
            out + (size_t)cell1 * C4 + c1, ys1, ye1, xs1, xe1);
    do_cell(fm + ((size_t)b2 * H_DIM * W_DIM) * C4 + c2,
            out + (size_t)cell2 * C4 + c2, ys2, ye2, xs2, xe2);
}

extern "C" void kernel_launch(void* const* d_in, const int* in_sizes, int n_in,
                              void* d_out, int out_size) {
    const float4* fm   = (const float4*)d_in[0];
    const int*    rois = (const int*)d_in[1];
    float4*       out  = (float4*)d_out;

    const int n_rois  = in_sizes[1] / 4;     // B*N = 128
    const int B       = 2;                   // fixed per problem shapes
    const int n_per_b = n_rois / B;          // N = 64

    // 12544 units, 2 per warp -> 6272 one-warp blocks
    dim3 grid(n_rois * NCELL, 1);            // u1 = bx*2+by in [0, 6272)
    grid.x = (n_rois * NCELL * 2) / 4;       // 3136
    grid.y = 2;
    roi_pool_kernel<<<grid, 32>>>(fm, rois, out, n_per_b);
}